// round 4
// baseline (speedup 1.0000x reference)
#include <cuda_runtime.h>
#include <cstdint>

#define BB    2048
#define TT    64
#define CC    1024
#define HH    16
#define DKK   8
#define M1M   512
#define M2M   128
#define SCALE_ 0.35355339059327373f
#define EPS_   1e-5f

// ---------------- device scratch (no allocations allowed) ----------------
__device__ float g_wq[HH * CC];          // 64 KB  : folded query projection
__device__ float g_pooled[BB * CC];      // 8 MB   : attention-pooled features
__device__ int   g_mask_mode;            // 0=u8, 1=i32, 2=f32

// ---------------- f32x2 packed-math helpers ----------------
__device__ __forceinline__ unsigned long long pk2(float lo, float hi) {
    unsigned long long r;
    asm("mov.b64 %0, {%1,%2};" : "=l"(r) : "f"(lo), "f"(hi));
    return r;
}
__device__ __forceinline__ void upk2(unsigned long long v, float& lo, float& hi) {
    asm("mov.b64 {%0,%1}, %2;" : "=f"(lo), "=f"(hi) : "l"(v));
}
__device__ __forceinline__ unsigned long long fma2(unsigned long long a,
                                                   unsigned long long b,
                                                   unsigned long long c) {
    unsigned long long d;
    asm("fma.rn.f32x2 %0, %1, %2, %3;" : "=l"(d) : "l"(a), "l"(b), "l"(c));
    return d;
}

// ---------------- K0: wq precompute + mask dtype fingerprint ----------------
__global__ void k_pre(const float* __restrict__ Wk,
                      const float* __restrict__ query,
                      const void*  __restrict__ kpm) {
    if (blockIdx.x < 64) {
        int idx = blockIdx.x * 256 + threadIdx.x;     // 0..16383
        int h = idx >> 10, c = idx & 1023;
        float s = 0.f;
        #pragma unroll
        for (int d = 0; d < DKK; d++)
            s += query[h * DKK + d] * Wk[c * (HH * DKK) + h * DKK + d];
        g_wq[h * CC + c] = s * SCALE_;
    } else {
        // mask dtype detection: scan first 32768 bytes.
        // f32: bytes outside {0,1}. i32 bool: only byte pos %4==0 can be 1.
        // u8 bool: ~50% ones at all byte positions.
        __shared__ int nonbin, oddpos;
        int tid = threadIdx.x;
        if (tid == 0) { nonbin = 0; oddpos = 0; }
        __syncthreads();
        const unsigned char* p = (const unsigned char*)kpm;
        int lnb = 0, lod = 0;
        int base = tid * 128;
        for (int i = 0; i < 128; i++) {
            unsigned char v = p[base + i];
            if (v > 1) lnb = 1;
            else if (v == 1 && ((base + i) & 3)) lod = 1;
        }
        if (lnb) atomicOr(&nonbin, 1);
        if (lod) atomicOr(&oddpos, 1);
        __syncthreads();
        if (tid == 0) g_mask_mode = nonbin ? 2 : (oddpos ? 0 : 1);
    }
}

// ---------------- K1: fused scores + masked softmax + pooling ----------------
// smem layout (floats): wq_s[16*1024] | xs[2][16*1024] | att[16*64] | mask[64]
#define WQ_OFF   0
#define XS_OFF   16384
#define ATT_OFF  49152
#define MSK_OFF  50176
#define SMEM1_F  50240

__device__ __forceinline__ void tile_async(float* dst, const float* src) {
    // 16 rows x 1024 floats, 256 threads, 16 x cp.async(16B) per thread
    int tid = threadIdx.x;
    #pragma unroll
    for (int i = 0; i < 16; i++) {
        int e = (tid + i * 256) * 4;
        uint32_t sa = (uint32_t)__cvta_generic_to_shared(dst + e);
        asm volatile("cp.async.cg.shared.global [%0], [%1], 16;\n"
                     :: "r"(sa), "l"(src + e));
    }
}

__global__ void __launch_bounds__(256, 1)
k_attn(const float* __restrict__ x, const void* __restrict__ kpm,
       float* __restrict__ attn_out) {
    extern __shared__ float smem[];
    float* wq_s  = smem + WQ_OFF;
    float* xs    = smem + XS_OFF;
    float* att_s = smem + ATT_OFF;
    int*   msk_s = (int*)(smem + MSK_OFF);

    const int b    = blockIdx.x;
    const int tid  = threadIdx.x;
    const int wid  = tid >> 5;
    const int lane = tid & 31;
    const float* xb = x + (size_t)b * (TT * CC);
    const int mode  = g_mask_mode;

    // prefetch tile 0
    tile_async(xs, xb);
    asm volatile("cp.async.commit_group;\n");

    // stage wq (coalesced float4)
    #pragma unroll 4
    for (int i = tid; i < 4096; i += 256)
        ((float4*)wq_s)[i] = ((const float4*)g_wq)[i];

    // mask
    if (tid < TT) {
        int mv;
        if (mode == 0)      mv = ((const unsigned char*)kpm)[b * TT + tid] != 0;
        else if (mode == 1) mv = ((const int*)kpm)[b * TT + tid] != 0;
        else                mv = ((const float*)kpm)[b * TT + tid] != 0.f;
        msk_s[tid] = mv;
    }

    const int rg = (wid & 3) * 4;       // 4 rows within tile
    const int h0 = (wid >> 2) * 8;      // 8 heads

    for (int tile = 0; tile < 4; tile++) {
        if (tile < 3) {
            tile_async(xs + ((tile + 1) & 1) * 16384, xb + (tile + 1) * 16384);
            asm volatile("cp.async.commit_group;\n");
            asm volatile("cp.async.wait_group 1;\n");
        } else {
            asm volatile("cp.async.wait_group 0;\n");
        }
        __syncthreads();

        const float* xt = xs + (tile & 1) * 16384;
        const float* xr0 = xt + (rg + 0) * CC;
        const float* xr1 = xt + (rg + 1) * CC;
        const float* xr2 = xt + (rg + 2) * CC;
        const float* xr3 = xt + (rg + 3) * CC;

        unsigned long long acc[4][8];
        #pragma unroll
        for (int r = 0; r < 4; r++)
            #pragma unroll
            for (int h = 0; h < 8; h++) acc[r][h] = 0ull;

        #pragma unroll
        for (int it = 0; it < 8; it++) {
            int c = lane * 4 + it * 128;
            float4 v0 = *(const float4*)(xr0 + c);
            float4 v1 = *(const float4*)(xr1 + c);
            float4 v2 = *(const float4*)(xr2 + c);
            float4 v3 = *(const float4*)(xr3 + c);
            unsigned long long xa0 = pk2(v0.x, v0.y), xb0 = pk2(v0.z, v0.w);
            unsigned long long xa1 = pk2(v1.x, v1.y), xb1 = pk2(v1.z, v1.w);
            unsigned long long xa2 = pk2(v2.x, v2.y), xb2 = pk2(v2.z, v2.w);
            unsigned long long xa3 = pk2(v3.x, v3.y), xb3 = pk2(v3.z, v3.w);
            #pragma unroll
            for (int h = 0; h < 8; h++) {
                float4 wv = *(const float4*)(wq_s + (h0 + h) * CC + c);
                unsigned long long wa = pk2(wv.x, wv.y), wb = pk2(wv.z, wv.w);
                acc[0][h] = fma2(xa0, wa, acc[0][h]); acc[0][h] = fma2(xb0, wb, acc[0][h]);
                acc[1][h] = fma2(xa1, wa, acc[1][h]); acc[1][h] = fma2(xb1, wb, acc[1][h]);
                acc[2][h] = fma2(xa2, wa, acc[2][h]); acc[2][h] = fma2(xb2, wb, acc[2][h]);
                acc[3][h] = fma2(xa3, wa, acc[3][h]); acc[3][h] = fma2(xb3, wb, acc[3][h]);
            }
        }

        // lane reduction: 32 (row,head) sums per warp
        float s[32];
        #pragma unroll
        for (int r = 0; r < 4; r++)
            #pragma unroll
            for (int h = 0; h < 8; h++) {
                float lo, hi; upk2(acc[r][h], lo, hi);
                s[r * 8 + h] = lo + hi;
            }
        #pragma unroll
        for (int off = 16; off; off >>= 1)
            #pragma unroll
            for (int i = 0; i < 32; i++)
                s[i] += __shfl_xor_sync(0xffffffffu, s[i], off);
        float myv = 0.f;
        #pragma unroll
        for (int i = 0; i < 32; i++) if (lane == i) myv = s[i];
        // lane i -> (row = i>>3, head = i&7); scores stored [h][t]
        att_s[(h0 + (lane & 7)) * TT + tile * 16 + rg + (lane >> 3)] = myv;
        __syncthreads();
    }

    // masked softmax per head row (8 warps x 2 heads)
    for (int h = wid; h < HH; h += 8) {
        float v0 = att_s[h * TT + lane];
        float v1 = att_s[h * TT + 32 + lane];
        int   m0 = msk_s[lane];
        int   m1 = msk_s[32 + lane];
        float a0 = m0 ? -3.4e38f : v0;
        float a1 = m1 ? -3.4e38f : v1;
        float mx = fmaxf(a0, a1);
        #pragma unroll
        for (int off = 16; off; off >>= 1)
            mx = fmaxf(mx, __shfl_xor_sync(0xffffffffu, mx, off));
        float e0 = m0 ? 0.f : __expf(v0 - mx);
        float e1 = m1 ? 0.f : __expf(v1 - mx);
        float sm = e0 + e1;
        #pragma unroll
        for (int off = 16; off; off >>= 1)
            sm += __shfl_xor_sync(0xffffffffu, sm, off);
        float inv = 1.f / sm;
        e0 *= inv; e1 *= inv;
        att_s[h * TT + lane]      = e0;
        att_s[h * TT + 32 + lane] = e1;
        attn_out[(size_t)b * (HH * TT) + h * TT + lane]      = e0;
        attn_out[(size_t)b * (HH * TT) + h * TT + 32 + lane] = e1;
    }
    __syncthreads();

    // pooling: pooled[c] = sum_t attn[c>>6][t] * x[t][c]   (x from L2)
    {
        int c4 = tid * 4;
        const float* at  = att_s + (c4 >> 6) * TT;
        const float* xp  = xb + c4;
        float ax = 0.f, ay = 0.f, az = 0.f, aw = 0.f;
        #pragma unroll 4
        for (int t = 0; t < TT; t++) {
            float a = at[t];
            float4 v = *(const float4*)(xp + t * CC);
            ax += a * v.x; ay += a * v.y; az += a * v.z; aw += a * v.w;
        }
        *(float4*)(g_pooled + (size_t)b * CC + c4) = make_float4(ax, ay, az, aw);
    }
}

// ---------------- K2: MLP (GEMM1 + LN + ReLU + GEMM2 + LN + ReLU) ----------------
// smem layout (floats): pt[1024*18] | ys[16*512] | y2s[16*128] | stats[64]
#define PT_OFF   0
#define PT_STR   18
#define YS_OFF   18432
#define Y2_OFF   26624
#define ST_OFF   28672
#define SMEM2_F  28736

__global__ void __launch_bounds__(256, 1)
k_mlp(const float* __restrict__ W1, const float* __restrict__ g1,
      const float* __restrict__ b1, const float* __restrict__ W2,
      const float* __restrict__ g2, const float* __restrict__ b2,
      float* __restrict__ out) {
    extern __shared__ float smem[];
    float* pt  = smem + PT_OFF;
    float* ys  = smem + YS_OFF;
    float* y2s = smem + Y2_OFF;
    float* mu1 = smem + ST_OFF;       // [16]
    float* rs1 = mu1 + 16;            // [16]
    float* mu2 = rs1 + 16;            // [16]
    float* rs2 = mu2 + 16;            // [16]

    const int b0   = blockIdx.x * 16;
    const int tid  = threadIdx.x;
    const int wid  = tid >> 5;
    const int lane = tid & 31;

    // stage pooled tile transposed: pt[k*18 + r]
    for (int i = tid; i < 4096; i += 256) {
        int r  = i >> 8;
        int k4 = (i & 255) * 4;
        float4 v = *(const float4*)(g_pooled + (size_t)(b0 + r) * CC + k4);
        pt[(k4 + 0) * PT_STR + r] = v.x;
        pt[(k4 + 1) * PT_STR + r] = v.y;
        pt[(k4 + 2) * PT_STR + r] = v.z;
        pt[(k4 + 3) * PT_STR + r] = v.w;
    }
    __syncthreads();

    // GEMM1: each thread owns columns (2*tid, 2*tid+1), 16 rows
    unsigned long long acc[16];
    #pragma unroll
    for (int r = 0; r < 16; r++) acc[r] = 0ull;
    const float2* w1p = (const float2*)W1 + tid;
    #pragma unroll 4
    for (int k = 0; k < CC; k++) {
        float2 w = w1p[k * (M1M / 2)];
        unsigned long long wp = pk2(w.x, w.y);
        const float* ptk = pt + k * PT_STR;
        #pragma unroll
        for (int rp = 0; rp < 8; rp++) {
            float2 xv = *(const float2*)(ptk + rp * 2);
            acc[2 * rp]     = fma2(pk2(xv.x, xv.x), wp, acc[2 * rp]);
            acc[2 * rp + 1] = fma2(pk2(xv.y, xv.y), wp, acc[2 * rp + 1]);
        }
    }
    #pragma unroll
    for (int r = 0; r < 16; r++) {
        float lo, hi; upk2(acc[r], lo, hi);
        *(float2*)(ys + r * M1M + 2 * tid) = make_float2(lo, hi);
    }
    __syncthreads();

    // LN1 statistics: warp wid handles rows wid, wid+8
    for (int r = wid; r < 16; r += 8) {
        float s = 0.f, ss = 0.f;
        #pragma unroll
        for (int j = 0; j < 16; j++) {
            float v = ys[r * M1M + lane + j * 32];
            s += v; ss += v * v;
        }
        #pragma unroll
        for (int off = 16; off; off >>= 1) {
            s  += __shfl_xor_sync(0xffffffffu, s, off);
            ss += __shfl_xor_sync(0xffffffffu, ss, off);
        }
        if (lane == 0) {
            float mu = s * (1.f / M1M);
            float var = ss * (1.f / M1M) - mu * mu;
            mu1[r] = mu;
            rs1[r] = rsqrtf(var + EPS_);
        }
    }
    __syncthreads();

    // normalize + relu in place
    {
        float2 gv = ((const float2*)g1)[tid];
        float2 bv = ((const float2*)b1)[tid];
        #pragma unroll
        for (int r = 0; r < 16; r++) {
            float m = mu1[r], rs = rs1[r];
            float2 v = *(float2*)(ys + r * M1M + 2 * tid);
            v.x = fmaxf(0.f, (v.x - m) * rs * gv.x + bv.x);
            v.y = fmaxf(0.f, (v.y - m) * rs * gv.y + bv.y);
            *(float2*)(ys + r * M1M + 2 * tid) = v;
        }
    }
    __syncthreads();

    // GEMM2: thread -> (m = tid&127, rows rb..rb+7)
    const int m  = tid & 127;
    const int rb = (tid >> 7) * 8;
    {
        float a2[8];
        #pragma unroll
        for (int j = 0; j < 8; j++) a2[j] = 0.f;
        #pragma unroll 2
        for (int k = 0; k < M1M; k++) {
            float w = W2[k * M2M + m];
            const float* yk = ys + rb * M1M + k;
            #pragma unroll
            for (int j = 0; j < 8; j++) a2[j] += yk[j * M1M] * w;
        }
        #pragma unroll
        for (int j = 0; j < 8; j++) y2s[(rb + j) * M2M + m] = a2[j];
    }
    __syncthreads();

    // LN2 statistics
    for (int r = wid; r < 16; r += 8) {
        float s = 0.f, ss = 0.f;
        #pragma unroll
        for (int j = 0; j < 4; j++) {
            float v = y2s[r * M2M + lane + j * 32];
            s += v; ss += v * v;
        }
        #pragma unroll
        for (int off = 16; off; off >>= 1) {
            s  += __shfl_xor_sync(0xffffffffu, s, off);
            ss += __shfl_xor_sync(0xffffffffu, ss, off);
        }
        if (lane == 0) {
            float mu = s * (1.f / M2M);
            float var = ss * (1.f / M2M) - mu * mu;
            mu2[r] = mu;
            rs2[r] = rsqrtf(var + EPS_);
        }
    }
    __syncthreads();

    // normalize + relu + write output (coalesced)
    {
        float gv = g2[m], bv = b2[m];
        #pragma unroll
        for (int j = 0; j < 8; j++) {
            int r = rb + j;
            float v = (y2s[r * M2M + m] - mu2[r]) * rs2[r] * gv + bv;
            out[(size_t)(b0 + r) * M2M + m] = fmaxf(0.f, v);
        }
    }
}

// ---------------- launcher ----------------
extern "C" void kernel_launch(void* const* d_in, const int* in_sizes, int n_in,
                              void* d_out, int out_size) {
    const float* x     = (const float*)d_in[0];
    // d_in[1] = temp_idx (unused by reference)
    const void*  kpm   = d_in[2];
    const float* Wk    = (const float*)d_in[3];
    // d_in[4] = bk : cancels in softmax, unused
    const float* query = (const float*)d_in[5];
    const float* W1    = (const float*)d_in[6];
    const float* g1    = (const float*)d_in[7];
    const float* b1    = (const float*)d_in[8];
    const float* W2    = (const float*)d_in[9];
    const float* g2    = (const float*)d_in[10];
    const float* b2    = (const float*)d_in[11];

    float* out_mlp  = (float*)d_out;                       // [B, 128]
    float* out_attn = (float*)d_out + (size_t)BB * M2M;    // [B, H, T]

    cudaFuncSetAttribute(k_attn, cudaFuncAttributeMaxDynamicSharedMemorySize,
                         SMEM1_F * 4);
    cudaFuncSetAttribute(k_mlp, cudaFuncAttributeMaxDynamicSharedMemorySize,
                         SMEM2_F * 4);

    k_pre<<<65, 256>>>(Wk, query, kpm);
    k_attn<<<BB, 256, SMEM1_F * 4>>>(x, kpm, out_attn);
    k_mlp<<<BB / 16, 256, SMEM2_F * 4>>>(W1, g1, b1, W2, g2, b2, out_mlp);
}

// round 5
// speedup vs baseline: 1.4100x; 1.4100x over previous
#include <cuda_runtime.h>
#include <cstdint>

#define BB    2048
#define TT    64
#define CC    1024
#define HH    16
#define DKK   8
#define M1M   512
#define M2M   128
#define SCALE_ 0.35355339059327373f
#define EPS_   1e-5f
#define NEGINF_ (-3.402823466e38f)

// ---------------- device scratch (no allocations allowed) ----------------
__device__ float g_wq[HH * CC];          // 64 KB  : folded query projection (scaled)
__device__ float g_pooled[BB * CC];      // 8 MB   : attention-pooled features
__device__ int   g_mask_mode;            // 0=u8, 1=i32, 2=f32

// ---------------- f32x2 packed-math helpers ----------------
__device__ __forceinline__ unsigned long long pk2(float lo, float hi) {
    unsigned long long r;
    asm("mov.b64 %0, {%1,%2};" : "=l"(r) : "f"(lo), "f"(hi));
    return r;
}
__device__ __forceinline__ void upk2(unsigned long long v, float& lo, float& hi) {
    asm("mov.b64 {%0,%1}, %2;" : "=f"(lo), "=f"(hi) : "l"(v));
}
__device__ __forceinline__ unsigned long long fma2(unsigned long long a,
                                                   unsigned long long b,
                                                   unsigned long long c) {
    unsigned long long d;
    asm("fma.rn.f32x2 %0, %1, %2, %3;" : "=l"(d) : "l"(a), "l"(b), "l"(c));
    return d;
}

// ---------------- K0: wq precompute (smem-staged, coalesced) + mask fingerprint ----
__global__ void k_pre(const float* __restrict__ Wk,
                      const float* __restrict__ query,
                      const void*  __restrict__ kpm) {
    __shared__ float wk_s[64 * 128];   // 32 KB slice of Wk
    __shared__ float q_s[128];
    const int tid = threadIdx.x;
    if (blockIdx.x < 16) {
        const int c_base = blockIdx.x * 64;
        // stage Wk rows [c_base, c_base+64) : 8192 floats, coalesced float4
        const float4* src = (const float4*)(Wk + c_base * (HH * DKK));
        #pragma unroll
        for (int i = 0; i < 8; i++)
            ((float4*)wk_s)[tid + i * 256] = src[tid + i * 256];
        if (tid < 128) q_s[tid] = query[tid] * SCALE_;
        __syncthreads();
        // thread -> (h = tid>>4, 4 c-values)
        const int h  = tid >> 4;
        const int cl = (tid & 15) * 4;
        #pragma unroll
        for (int j = 0; j < 4; j++) {
            float s = 0.f;
            #pragma unroll
            for (int d = 0; d < DKK; d++)
                s += q_s[h * DKK + d] * wk_s[(cl + j) * 128 + h * DKK + d];
            g_wq[h * CC + c_base + cl + j] = s;
        }
    } else {
        // mask dtype detection: scan first 32768 bytes.
        __shared__ int nonbin, oddpos;
        if (tid == 0) { nonbin = 0; oddpos = 0; }
        __syncthreads();
        const unsigned char* p = (const unsigned char*)kpm;
        int lnb = 0, lod = 0;
        int base = tid * 128;
        for (int i = 0; i < 128; i++) {
            unsigned char v = p[base + i];
            if (v > 1) lnb = 1;
            else if (v == 1 && ((base + i) & 3)) lod = 1;
        }
        if (lnb) atomicOr(&nonbin, 1);
        if (lod) atomicOr(&oddpos, 1);
        __syncthreads();
        if (tid == 0) g_mask_mode = nonbin ? 2 : (oddpos ? 0 : 1);
    }
}

// ---------------- K1: fused scores + flash softmax + pooling (single x pass) -----
// smem floats: wq[16384] | xs[2][16384] | att[1024] | p[256] | mrun[16] srun[16]
//              fsc[16] | msk[64]
#define WQ_OFF   0
#define XS_OFF   16384
#define ATT_OFF  49152
#define P_OFF    50176
#define MR_OFF   50432
#define SR_OFF   50448
#define FS_OFF   50464
#define MSK_OFF  50480
#define SMEM1_F  50544

__device__ __forceinline__ void tile_async(float* dst, const float* src) {
    int tid = threadIdx.x;
    #pragma unroll
    for (int i = 0; i < 16; i++) {
        int e = (tid + i * 256) * 4;
        uint32_t sa = (uint32_t)__cvta_generic_to_shared(dst + e);
        asm volatile("cp.async.cg.shared.global [%0], [%1], 16;\n"
                     :: "r"(sa), "l"(src + e));
    }
}

__global__ void __launch_bounds__(256, 1)
k_attn(const float* __restrict__ x, const void* __restrict__ kpm,
       float* __restrict__ attn_out) {
    extern __shared__ float smem[];
    float* wq_s  = smem + WQ_OFF;
    float* xs    = smem + XS_OFF;
    float* att_s = smem + ATT_OFF;
    float* p_s   = smem + P_OFF;
    float* mrun  = smem + MR_OFF;
    float* srun  = smem + SR_OFF;
    float* fsc   = smem + FS_OFF;
    int*   msk_s = (int*)(smem + MSK_OFF);

    const int b    = blockIdx.x;
    const int tid  = threadIdx.x;
    const int wid  = tid >> 5;
    const int lane = tid & 31;
    const float* xb = x + (size_t)b * (TT * CC);
    const int mode  = g_mask_mode;

    // prefetch tile 0
    tile_async(xs, xb);
    asm volatile("cp.async.commit_group;\n");

    // stage wq (coalesced float4)
    #pragma unroll 4
    for (int i = tid; i < 4096; i += 256)
        ((float4*)wq_s)[i] = ((const float4*)g_wq)[i];

    if (tid < TT) {
        int mv;
        if (mode == 0)      mv = ((const unsigned char*)kpm)[b * TT + tid] != 0;
        else if (mode == 1) mv = ((const int*)kpm)[b * TT + tid] != 0;
        else                mv = ((const float*)kpm)[b * TT + tid] != 0.f;
        msk_s[tid] = mv;
    }
    if (tid < HH) { mrun[tid] = NEGINF_; srun[tid] = 0.f; }

    const int rg = (wid & 3) * 4;       // 4 rows within tile
    const int h0 = (wid >> 2) * 8;      // 8 heads

    // per-thread pooled accumulator: 4 channels
    float4 pacc = make_float4(0.f, 0.f, 0.f, 0.f);
    const int hc = tid >> 4;            // head owning channels [tid*4, tid*4+4)

    for (int tile = 0; tile < 4; tile++) {
        if (tile < 3) {
            tile_async(xs + ((tile + 1) & 1) * 16384, xb + (tile + 1) * 16384);
            asm volatile("cp.async.commit_group;\n");
            asm volatile("cp.async.wait_group 1;\n");
        } else {
            asm volatile("cp.async.wait_group 0;\n");
        }
        __syncthreads();

        float* xt = xs + (tile & 1) * 16384;
        const float* xr0 = xt + (rg + 0) * CC;
        const float* xr1 = xt + (rg + 1) * CC;
        const float* xr2 = xt + (rg + 2) * CC;
        const float* xr3 = xt + (rg + 3) * CC;

        unsigned long long acc[4][8];
        #pragma unroll
        for (int r = 0; r < 4; r++)
            #pragma unroll
            for (int h = 0; h < 8; h++) acc[r][h] = 0ull;

        #pragma unroll
        for (int it = 0; it < 8; it++) {
            int c = lane * 4 + it * 128;
            float4 v0 = *(const float4*)(xr0 + c);
            float4 v1 = *(const float4*)(xr1 + c);
            float4 v2 = *(const float4*)(xr2 + c);
            float4 v3 = *(const float4*)(xr3 + c);
            unsigned long long xa0 = pk2(v0.x, v0.y), xb0 = pk2(v0.z, v0.w);
            unsigned long long xa1 = pk2(v1.x, v1.y), xb1 = pk2(v1.z, v1.w);
            unsigned long long xa2 = pk2(v2.x, v2.y), xb2 = pk2(v2.z, v2.w);
            unsigned long long xa3 = pk2(v3.x, v3.y), xb3 = pk2(v3.z, v3.w);
            #pragma unroll
            for (int h = 0; h < 8; h++) {
                float4 wv = *(const float4*)(wq_s + (h0 + h) * CC + c);
                unsigned long long wa = pk2(wv.x, wv.y), wb = pk2(wv.z, wv.w);
                acc[0][h] = fma2(xa0, wa, acc[0][h]); acc[0][h] = fma2(xb0, wb, acc[0][h]);
                acc[1][h] = fma2(xa1, wa, acc[1][h]); acc[1][h] = fma2(xb1, wb, acc[1][h]);
                acc[2][h] = fma2(xa2, wa, acc[2][h]); acc[2][h] = fma2(xb2, wb, acc[2][h]);
                acc[3][h] = fma2(xa3, wa, acc[3][h]); acc[3][h] = fma2(xb3, wb, acc[3][h]);
            }
        }

        // staggered per-row reduction (max 8 partials live; acc row dies after unpack)
        #pragma unroll
        for (int r = 0; r < 4; r++) {
            float sv[8];
            #pragma unroll
            for (int h = 0; h < 8; h++) {
                float lo, hi; upk2(acc[r][h], lo, hi);
                sv[h] = lo + hi;
            }
            #pragma unroll
            for (int off = 16; off; off >>= 1)
                #pragma unroll
                for (int h = 0; h < 8; h++)
                    sv[h] += __shfl_xor_sync(0xffffffffu, sv[h], off);
            float v = sv[0];
            #pragma unroll
            for (int h = 1; h < 8; h++) v = (lane == h) ? sv[h] : v;
            if (lane < 8)
                att_s[(h0 + lane) * TT + tile * 16 + rg + r] = v;
        }
        __syncthreads();

        // ---- flash update: warp w handles heads 2w, 2w+1 (16 lanes each) ----
        {
            const int h  = wid * 2 + (lane >> 4);
            const int tt = lane & 15;
            const int tg = tile * 16 + tt;
            float s_raw  = att_s[h * TT + tg];
            int   msk    = msk_s[tg];
            float sm     = msk ? NEGINF_ : s_raw;
            float tmax   = sm;
            #pragma unroll
            for (int off = 8; off; off >>= 1)
                tmax = fmaxf(tmax, __shfl_xor_sync(0xffffffffu, tmax, off));
            float m_old = mrun[h];
            float m_new = fmaxf(m_old, tmax);
            float p     = msk ? 0.f : __expf(s_raw - m_new);
            float psum  = p;
            #pragma unroll
            for (int off = 8; off; off >>= 1)
                psum += __shfl_xor_sync(0xffffffffu, psum, off);
            float f = __expf(m_old - m_new);
            p_s[h * 16 + tt] = p;
            if ((lane & 15) == 0) {
                mrun[h] = m_new;
                srun[h] = srun[h] * f + psum;
                fsc[h]  = f;
            }
        }
        __syncthreads();

        // ---- pooled accumulation from resident smem tile ----
        {
            float f = fsc[hc];
            pacc.x *= f; pacc.y *= f; pacc.z *= f; pacc.w *= f;
            const float* xp = xt + tid * 4;
            const float* pp = p_s + hc * 16;
            #pragma unroll
            for (int t = 0; t < 16; t++) {
                float p = pp[t];
                float4 v = *(const float4*)(xp + t * CC);
                pacc.x += p * v.x; pacc.y += p * v.y;
                pacc.z += p * v.z; pacc.w += p * v.w;
            }
        }
        __syncthreads();
    }

    // ---- finalize: attn output + pooled ----
    {
        const int h  = tid >> 4;
        const int t4 = (tid & 15) * 4;
        float m   = mrun[h];
        float inv = 1.f / srun[h];
        float4 o;
        float* op = &o.x;
        #pragma unroll
        for (int j = 0; j < 4; j++) {
            int t = t4 + j;
            op[j] = msk_s[t] ? 0.f : __expf(att_s[h * TT + t] - m) * inv;
        }
        *(float4*)(attn_out + (size_t)b * (HH * TT) + h * TT + t4) = o;

        float invp = 1.f / srun[hc];
        pacc.x *= invp; pacc.y *= invp; pacc.z *= invp; pacc.w *= invp;
        *(float4*)(g_pooled + (size_t)b * CC + tid * 4) = pacc;
    }
}

// ---------------- K2: MLP (GEMM1 + LN + ReLU + GEMM2 + LN + ReLU) ----------------
#define PT_OFF   0
#define PT_STR   18
#define YS_OFF   18432
#define Y2_OFF   26624
#define ST_OFF   28672
#define SMEM2_F  28736

__global__ void __launch_bounds__(256, 1)
k_mlp(const float* __restrict__ W1, const float* __restrict__ g1,
      const float* __restrict__ b1, const float* __restrict__ W2,
      const float* __restrict__ g2, const float* __restrict__ b2,
      float* __restrict__ out) {
    extern __shared__ float smem[];
    float* pt  = smem + PT_OFF;
    float* ys  = smem + YS_OFF;
    float* y2s = smem + Y2_OFF;
    float* mu1 = smem + ST_OFF;
    float* rs1 = mu1 + 16;
    float* mu2 = rs1 + 16;
    float* rs2 = mu2 + 16;

    const int b0   = blockIdx.x * 16;
    const int tid  = threadIdx.x;
    const int wid  = tid >> 5;
    const int lane = tid & 31;

    for (int i = tid; i < 4096; i += 256) {
        int r  = i >> 8;
        int k4 = (i & 255) * 4;
        float4 v = *(const float4*)(g_pooled + (size_t)(b0 + r) * CC + k4);
        pt[(k4 + 0) * PT_STR + r] = v.x;
        pt[(k4 + 1) * PT_STR + r] = v.y;
        pt[(k4 + 2) * PT_STR + r] = v.z;
        pt[(k4 + 3) * PT_STR + r] = v.w;
    }
    __syncthreads();

    unsigned long long acc[16];
    #pragma unroll
    for (int r = 0; r < 16; r++) acc[r] = 0ull;
    const float2* w1p = (const float2*)W1 + tid;
    #pragma unroll 4
    for (int k = 0; k < CC; k++) {
        float2 w = w1p[k * (M1M / 2)];
        unsigned long long wp = pk2(w.x, w.y);
        const float* ptk = pt + k * PT_STR;
        #pragma unroll
        for (int rp = 0; rp < 8; rp++) {
            float2 xv = *(const float2*)(ptk + rp * 2);
            acc[2 * rp]     = fma2(pk2(xv.x, xv.x), wp, acc[2 * rp]);
            acc[2 * rp + 1] = fma2(pk2(xv.y, xv.y), wp, acc[2 * rp + 1]);
        }
    }
    #pragma unroll
    for (int r = 0; r < 16; r++) {
        float lo, hi; upk2(acc[r], lo, hi);
        *(float2*)(ys + r * M1M + 2 * tid) = make_float2(lo, hi);
    }
    __syncthreads();

    for (int r = wid; r < 16; r += 8) {
        float s = 0.f, ss = 0.f;
        #pragma unroll
        for (int j = 0; j < 16; j++) {
            float v = ys[r * M1M + lane + j * 32];
            s += v; ss += v * v;
        }
        #pragma unroll
        for (int off = 16; off; off >>= 1) {
            s  += __shfl_xor_sync(0xffffffffu, s, off);
            ss += __shfl_xor_sync(0xffffffffu, ss, off);
        }
        if (lane == 0) {
            float mu = s * (1.f / M1M);
            float var = ss * (1.f / M1M) - mu * mu;
            mu1[r] = mu;
            rs1[r] = rsqrtf(var + EPS_);
        }
    }
    __syncthreads();

    {
        float2 gv = ((const float2*)g1)[tid];
        float2 bv = ((const float2*)b1)[tid];
        #pragma unroll
        for (int r = 0; r < 16; r++) {
            float m = mu1[r], rs = rs1[r];
            float2 v = *(float2*)(ys + r * M1M + 2 * tid);
            v.x = fmaxf(0.f, (v.x - m) * rs * gv.x + bv.x);
            v.y = fmaxf(0.f, (v.y - m) * rs * gv.y + bv.y);
            *(float2*)(ys + r * M1M + 2 * tid) = v;
        }
    }
    __syncthreads();

    const int m  = tid & 127;
    const int rb = (tid >> 7) * 8;
    {
        float a2[8];
        #pragma unroll
        for (int j = 0; j < 8; j++) a2[j] = 0.f;
        #pragma unroll 2
        for (int k = 0; k < M1M; k++) {
            float w = W2[k * M2M + m];
            const float* yk = ys + rb * M1M + k;
            #pragma unroll
            for (int j = 0; j < 8; j++) a2[j] += yk[j * M1M] * w;
        }
        #pragma unroll
        for (int j = 0; j < 8; j++) y2s[(rb + j) * M2M + m] = a2[j];
    }
    __syncthreads();

    for (int r = wid; r < 16; r += 8) {
        float s = 0.f, ss = 0.f;
        #pragma unroll
        for (int j = 0; j < 4; j++) {
            float v = y2s[r * M2M + lane + j * 32];
            s += v; ss += v * v;
        }
        #pragma unroll
        for (int off = 16; off; off >>= 1) {
            s  += __shfl_xor_sync(0xffffffffu, s, off);
            ss += __shfl_xor_sync(0xffffffffu, ss, off);
        }
        if (lane == 0) {
            float mu = s * (1.f / M2M);
            float var = ss * (1.f / M2M) - mu * mu;
            mu2[r] = mu;
            rs2[r] = rsqrtf(var + EPS_);
        }
    }
    __syncthreads();

    {
        float gv = g2[m], bv = b2[m];
        #pragma unroll
        for (int j = 0; j < 8; j++) {
            int r = rb + j;
            float v = (y2s[r * M2M + m] - mu2[r]) * rs2[r] * gv + bv;
            out[(size_t)(b0 + r) * M2M + m] = fmaxf(0.f, v);
        }
    }
}

// ---------------- launcher ----------------
extern "C" void kernel_launch(void* const* d_in, const int* in_sizes, int n_in,
                              void* d_out, int out_size) {
    const float* x     = (const float*)d_in[0];
    const void*  kpm   = d_in[2];
    const float* Wk    = (const float*)d_in[3];
    const float* query = (const float*)d_in[5];
    const float* W1    = (const float*)d_in[6];
    const float* g1    = (const float*)d_in[7];
    const float* b1    = (const float*)d_in[8];
    const float* W2    = (const float*)d_in[9];
    const float* g2    = (const float*)d_in[10];
    const float* b2    = (const float*)d_in[11];

    float* out_mlp  = (float*)d_out;                       // [B, 128]
    float* out_attn = (float*)d_out + (size_t)BB * M2M;    // [B, H, T]

    cudaFuncSetAttribute(k_attn, cudaFuncAttributeMaxDynamicSharedMemorySize,
                         SMEM1_F * 4);
    cudaFuncSetAttribute(k_mlp, cudaFuncAttributeMaxDynamicSharedMemorySize,
                         SMEM2_F * 4);

    k_pre<<<17, 256>>>(Wk, query, kpm);
    k_attn<<<BB, 256, SMEM1_F * 4>>>(x, kpm, out_attn);
    k_mlp<<<BB / 16, 256, SMEM2_F * 4>>>(W1, g1, b1, W2, g2, b2, out_mlp);
}